// round 1
// baseline (speedup 1.0000x reference)
#include <cuda_runtime.h>

// EmbedGraphConv: out[n] = norm_r[n] * sum_{e: dst[e]=n} (embedding[feat[src[e]]] * norm_l[src[e]]) + bias
// Strategy: counting-sort edges by dst -> atomic-free warp-per-node aggregation.
// All large working sets (h, out, emb, edges) fit in GB300's ~126MB L2.

#define NN 50000
#define NE 800000
#define DD 128

// Scratch (device globals: allocation is forbidden by harness rules)
__device__ int   g_out_deg[NN];
__device__ int   g_in_deg[NN];
__device__ int   g_offsets[NN];
__device__ int   g_cursor[NN];
__device__ int   g_sorted_src[NE];
__device__ float g_h[(size_t)NN * DD];   // 25.6 MB, L2-resident

__global__ void k_zero(int n) {
    int i = blockIdx.x * blockDim.x + threadIdx.x;
    if (i < n) { g_out_deg[i] = 0; g_in_deg[i] = 0; g_cursor[i] = 0; }
}

__global__ void k_hist(const int* __restrict__ src, const int* __restrict__ dst, int e) {
    int i = blockIdx.x * blockDim.x + threadIdx.x;
    if (i < e) {
        atomicAdd(&g_out_deg[src[i]], 1);
        atomicAdd(&g_in_deg[dst[i]], 1);
    }
}

// Exclusive scan of in_deg over NN bins: single block, 1024 threads, chunked.
__global__ void k_scan(int n) {
    __shared__ int sh[1024];
    int t = threadIdx.x;
    int chunk = (n + 1023) / 1024;
    int lo = t * chunk;
    int hi = min(lo + chunk, n);
    int s = 0;
    for (int i = lo; i < hi; i++) s += g_in_deg[i];
    sh[t] = s;
    __syncthreads();
    // Hillis–Steele inclusive scan over 1024 partials
    for (int off = 1; off < 1024; off <<= 1) {
        int v = (t >= off) ? sh[t - off] : 0;
        __syncthreads();
        sh[t] += v;
        __syncthreads();
    }
    int run = (t == 0) ? 0 : sh[t - 1];
    for (int i = lo; i < hi; i++) { g_offsets[i] = run; run += g_in_deg[i]; }
}

// Counting-sort scatter: place src of each edge into dst-sorted order.
__global__ void k_scatter(const int* __restrict__ src, const int* __restrict__ dst, int e) {
    int i = blockIdx.x * blockDim.x + threadIdx.x;
    if (i < e) {
        int d = dst[i];
        int pos = g_offsets[d] + atomicAdd(&g_cursor[d], 1);
        g_sorted_src[pos] = src[i];
    }
}

// Materialize h[n] = embedding[feat[n]] * out_deg[n]^{-1/2}  (float4-vectorized)
__global__ void k_build_h(const int* __restrict__ feat, const float4* __restrict__ emb, int n) {
    int idx = blockIdx.x * blockDim.x + threadIdx.x;   // one thread per float4; DD/4 = 32 per node
    if (idx < n * (DD / 4)) {
        int node = idx >> 5;
        int c    = idx & 31;
        float nl = rsqrtf((float)max(g_out_deg[node], 1));
        float4 v = emb[(size_t)feat[node] * 32 + c];
        v.x *= nl; v.y *= nl; v.z *= nl; v.w *= nl;
        reinterpret_cast<float4*>(g_h)[idx] = v;
    }
}

// Warp-per-node aggregation: each lane owns one float4 slice of D=128.
__global__ void k_agg(const float4* __restrict__ bias4, float4* __restrict__ out4, int n) {
    int warp = (blockIdx.x * blockDim.x + threadIdx.x) >> 5;
    int lane = threadIdx.x & 31;
    if (warp >= n) return;

    int start = g_offsets[warp];
    int cnt   = g_in_deg[warp];
    const float4* h4 = reinterpret_cast<const float4*>(g_h);

    float4 acc = make_float4(0.f, 0.f, 0.f, 0.f);
    int i = 0;
    // unroll-by-2 for MLP: two independent index loads + two independent row loads
    for (; i + 1 < cnt; i += 2) {
        int s0 = g_sorted_src[start + i];
        int s1 = g_sorted_src[start + i + 1];
        float4 a = h4[(size_t)s0 * 32 + lane];
        float4 b = h4[(size_t)s1 * 32 + lane];
        acc.x += a.x + b.x;
        acc.y += a.y + b.y;
        acc.z += a.z + b.z;
        acc.w += a.w + b.w;
    }
    if (i < cnt) {
        int s0 = g_sorted_src[start + i];
        float4 a = h4[(size_t)s0 * 32 + lane];
        acc.x += a.x; acc.y += a.y; acc.z += a.z; acc.w += a.w;
    }

    float nr = rsqrtf((float)max(cnt, 1));
    float4 bv = bias4[lane];
    float4 o;
    o.x = acc.x * nr + bv.x;
    o.y = acc.y * nr + bv.y;
    o.z = acc.z * nr + bv.z;
    o.w = acc.w * nr + bv.w;
    out4[(size_t)warp * 32 + lane] = o;
}

extern "C" void kernel_launch(void* const* d_in, const int* in_sizes, int n_in,
                              void* d_out, int out_size) {
    const int*    feat = (const int*)d_in[0];
    const int*    src  = (const int*)d_in[1];
    const int*    dst  = (const int*)d_in[2];
    const float*  emb  = (const float*)d_in[3];
    const float*  bias = (const float*)d_in[4];
    float*        out  = (float*)d_out;

    int n = in_sizes[0];   // 50000
    int e = in_sizes[1];   // 800000

    const int T = 256;
    k_zero   <<<(n + T - 1) / T, T>>>(n);
    k_hist   <<<(e + T - 1) / T, T>>>(src, dst, e);
    k_scan   <<<1, 1024>>>(n);
    k_scatter<<<(e + T - 1) / T, T>>>(src, dst, e);
    k_build_h<<<(n * (DD / 4) + T - 1) / T, T>>>(feat, (const float4*)emb, n);
    k_agg    <<<(n * 32 + T - 1) / T, T>>>((const float4*)bias, (float4*)out, n);
}